// round 6
// baseline (speedup 1.0000x reference)
#include <cuda_runtime.h>

// DiffeqSolver: RK4 over autonomous MLP dynamics f(y) = tanh(y@W1+b1)@W2 + b2
// Shapes: S=3, B=1024 -> ROWS=3072 independent rows; D=32, H=128, T=256.
//
// Design: 8 threads per row (group g=0..7), each owning hidden units
// j = g + 8*i (i=0..15). Warp = 4 rows x 8 groups. State y (32 floats) is
// replicated across the 8 group threads as 16 packed f32x2 values.
// Per f-eval: each thread computes 16 h_j (dot over D via packed FMA,
// W1 column read from smem with 4-row broadcast), then scatters h_j * W2[j,:]
// into 16 packed partial accumulators. Partials are reduced across the 8
// group lanes with a shfl_xor butterfly (bit-identical replicas -> all lanes
// hold full k). No __syncthreads in the main loop; warps are autonomous.
// Weights live in smem, padded to stride 36 floats so the 8 distinct
// j-columns per warp access hit distinct banks under LDS.128.

#define NROWS 3072
#define DIM   32
#define HID   128
#define NT    256
#define RPB   8        // rows per block
#define TPB   64       // threads per block (8 rows * 8 group-threads)
#define NBLK  (NROWS / RPB)   // 384
#define WST   36       // padded float stride for weight rows in smem

typedef unsigned long long ull;

__device__ __forceinline__ ull fma2(ull a, ull b, ull c) {
    ull d;
    asm("fma.rn.f32x2 %0, %1, %2, %3;" : "=l"(d) : "l"(a), "l"(b), "l"(c));
    return d;
}
__device__ __forceinline__ ull add2(ull a, ull b) {
    ull d;
    asm("add.rn.f32x2 %0, %1, %2;" : "=l"(d) : "l"(a), "l"(b));
    return d;
}
__device__ __forceinline__ ull pack2(float lo, float hi) {
    ull d;
    asm("mov.b64 %0, {%1, %2};" : "=l"(d) : "f"(lo), "f"(hi));
    return d;
}
__device__ __forceinline__ void unpack2(ull v, float& lo, float& hi) {
    asm("mov.b64 {%0, %1}, %2;" : "=f"(lo), "=f"(hi) : "l"(v));
}

// fast, accurate tanh: 1 - 2/(exp(2x)+1). __expf = 1 MUFU.EX2 (+ scale),
// __fdividef = MUFU.RCP + mul. ~1e-7 abs error; saturates correctly at +/-inf.
__device__ __forceinline__ float tanh_fast(float x) {
    float e = __expf(2.0f * x);
    return 1.0f - __fdividef(2.0f, e + 1.0f);
}

// One f evaluation for this thread's row. yin2: 16 packed f32x2 (the full
// 32-dim input, replicated per group thread). kout2: full f(y), packed.
__device__ __forceinline__ void feval(
    const ull* __restrict__ yin2, ull* __restrict__ kout2, int g,
    const float* __restrict__ w1s, const float* __restrict__ w2s,
    const float* __restrict__ b1s, const ull* __restrict__ b2s)
{
    ull p2[16];
#pragma unroll
    for (int d = 0; d < 16; ++d) p2[d] = 0ull;   // packed (0.0f, 0.0f)

#pragma unroll 4
    for (int i = 0; i < 16; ++i) {
        const int j = g + 8 * i;
        // dot(yin, W1[:, j]) with 4 independent packed partial sums
        const ulonglong2* w1p = reinterpret_cast<const ulonglong2*>(w1s + j * WST);
        ull d0 = 0ull, d1 = 0ull, d2 = 0ull, d3 = 0ull;
#pragma unroll
        for (int q = 0; q < 4; ++q) {
            ulonglong2 wa = w1p[2 * q];
            ulonglong2 wb = w1p[2 * q + 1];
            d0 = fma2(yin2[4 * q + 0], wa.x, d0);
            d1 = fma2(yin2[4 * q + 1], wa.y, d1);
            d2 = fma2(yin2[4 * q + 2], wb.x, d2);
            d3 = fma2(yin2[4 * q + 3], wb.y, d3);
        }
        ull ds = add2(add2(d0, d1), add2(d2, d3));
        float lo, hi;
        unpack2(ds, lo, hi);
        float h = tanh_fast(lo + hi + b1s[j]);
        ull hh = pack2(h, h);

        // scatter: p[d] += h * W2[j][d], 16 independent packed FMAs
        const ulonglong2* w2p = reinterpret_cast<const ulonglong2*>(w2s + j * WST);
#pragma unroll
        for (int q = 0; q < 8; ++q) {
            ulonglong2 w = w2p[q];
            p2[2 * q + 0] = fma2(hh, w.x, p2[2 * q + 0]);
            p2[2 * q + 1] = fma2(hh, w.y, p2[2 * q + 1]);
        }
    }

    // butterfly reduction across the 8 group lanes (lanes r*8+g, masks 1,2,4).
    // All replicas are bit-identical afterward.
#pragma unroll
    for (int m = 1; m < 8; m <<= 1) {
#pragma unroll
        for (int d = 0; d < 16; ++d) {
            ull o = __shfl_xor_sync(0xffffffffu, p2[d], m);
            p2[d] = add2(p2[d], o);
        }
    }

#pragma unroll
    for (int d = 0; d < 16; ++d) kout2[d] = add2(p2[d], b2s[d]);
}

__global__ __launch_bounds__(TPB)
void rk4_mlp_kernel(
    const float* __restrict__ first_point,   // [S*B, D] rows
    const float* __restrict__ time_steps,    // [T]
    const float* __restrict__ W1,            // [D, H]
    const float* __restrict__ b1,            // [H]
    const float* __restrict__ W2,            // [H, D]
    const float* __restrict__ b2,            // [D]
    float* __restrict__ out)                 // [S*B, T, D]
{
    __shared__ float w1s[HID * WST];   // W1 transposed: w1s[j*WST + d]
    __shared__ float w2s[HID * WST];   // W2 as-is:      w2s[j*WST + d]
    __shared__ float b1s[HID];
    __shared__ ull   b2s[DIM / 2];
    __shared__ float tss[NT];

    const int tid = threadIdx.x;

    // ---- stage weights into smem ----
    for (int idx = tid; idx < DIM * HID; idx += TPB) {
        int d = idx / HID, j = idx % HID;      // W1[d][j]
        w1s[j * WST + d] = W1[idx];
    }
    for (int idx = tid; idx < HID * DIM; idx += TPB) {
        int j = idx / DIM, d = idx % DIM;      // W2[j][d]
        w2s[j * WST + d] = W2[idx];
    }
    for (int idx = tid; idx < HID; idx += TPB) b1s[idx] = b1[idx];
    if (tid < DIM / 2) b2s[tid] = pack2(b2[2 * tid], b2[2 * tid + 1]);
    for (int idx = tid; idx < NT; idx += TPB) tss[idx] = time_steps[idx];
    __syncthreads();

    const int g   = tid & 7;                       // group id within row
    const int rid = blockIdx.x * RPB + (tid >> 3); // global row

    // ---- load initial state (replicated across the 8 group threads) ----
    ull y2[16], acc2[16], yin2[16], k2[16];
    const ulonglong2* fp =
        reinterpret_cast<const ulonglong2*>(first_point + (size_t)rid * DIM);
#pragma unroll
    for (int q = 0; q < 8; ++q) {
        ulonglong2 v = fp[q];
        y2[2 * q] = v.x;
        y2[2 * q + 1] = v.y;
    }

    float* outrow = out + (size_t)rid * (NT * DIM);

    // t = 0: write first_point (thread g writes dims 4g..4g+3)
    {
        ulonglong2 st;
        st.x = y2[2 * g];
        st.y = y2[2 * g + 1];
        *reinterpret_cast<ulonglong2*>(outrow + 4 * g) = st;
    }

    // ---- RK4 time loop (sequential) ----
#pragma unroll 1
    for (int t = 0; t < NT - 1; ++t) {
        const float dt  = tss[t + 1] - tss[t];
        const ull dt6p = pack2(dt * (1.0f / 6.0f), dt * (1.0f / 6.0f));
        const ull dt3p = pack2(dt * (1.0f / 3.0f), dt * (1.0f / 3.0f));
        const ull dthp = pack2(0.5f * dt, 0.5f * dt);
        const ull dtfp = pack2(dt, dt);

        // k1
        feval(y2, k2, g, w1s, w2s, b1s, b2s);
#pragma unroll
        for (int d = 0; d < 16; ++d) {
            acc2[d] = fma2(dt6p, k2[d], y2[d]);
            yin2[d] = fma2(dthp, k2[d], y2[d]);
        }
        // k2
        feval(yin2, k2, g, w1s, w2s, b1s, b2s);
#pragma unroll
        for (int d = 0; d < 16; ++d) {
            acc2[d] = fma2(dt3p, k2[d], acc2[d]);
            yin2[d] = fma2(dthp, k2[d], y2[d]);
        }
        // k3
        feval(yin2, k2, g, w1s, w2s, b1s, b2s);
#pragma unroll
        for (int d = 0; d < 16; ++d) {
            acc2[d] = fma2(dt3p, k2[d], acc2[d]);
            yin2[d] = fma2(dtfp, k2[d], y2[d]);
        }
        // k4
        feval(yin2, k2, g, w1s, w2s, b1s, b2s);
#pragma unroll
        for (int d = 0; d < 16; ++d) {
            y2[d] = fma2(dt6p, k2[d], acc2[d]);
        }

        // store y_{t+1}: 8 threads cover the 128B row segment, coalesced
        ulonglong2 st;
        st.x = y2[2 * g];
        st.y = y2[2 * g + 1];
        *reinterpret_cast<ulonglong2*>(outrow + (size_t)(t + 1) * DIM + 4 * g) = st;
    }
}

extern "C" void kernel_launch(void* const* d_in, const int* in_sizes, int n_in,
                              void* d_out, int out_size) {
    const float* first_point = (const float*)d_in[0];  // [3,1024,32]
    const float* time_steps  = (const float*)d_in[1];  // [256]
    const float* W1          = (const float*)d_in[2];  // [32,128]
    const float* b1          = (const float*)d_in[3];  // [128]
    const float* W2          = (const float*)d_in[4];  // [128,32]
    const float* b2          = (const float*)d_in[5];  // [32]
    float* out = (float*)d_out;                        // [3,1024,256,32]

    rk4_mlp_kernel<<<NBLK, TPB>>>(first_point, time_steps, W1, b1, W2, b2, out);
}

// round 7
// speedup vs baseline: 1.1209x; 1.1209x over previous
#include <cuda_runtime.h>

// RK4 over f(y) = tanh(y@W1+b1)@W2 + b2.  S*B=3072 rows, D=32, H=128, T=256.
//
// Quarter-slot layout: lane = (g = lane&7, s = lane>>3).
//   - lane owns hidden units j = g + 8i  (i = 0..15)
//   - lane owns state-quarter dims [8s .. 8s+7]  (4 packed f32x2 regs / row)
// One warp carries 4 rows; each weight value is loaded ONCE per feval and
// reused across all 4 rows (4x smem-crossbar cut vs. round-4 kernel).
// Weights are repacked in smem as [i][lane] float4 so every LDS.128 moves
// 512B of all-unique data (zero broadcast waste).
// Dot: per-quarter packed FMA -> 2-round shfl butterfly over s (row-pair
// packed). tanh. Scatter: lane accumulates its own k-quarter over its own
// j's; 3-round butterfly over g completes k. State ends up replicated across
// the 8 g-lanes; lanes g<4 write row g's quarter to gmem (coalesced 128B/row).

#define DIM   32
#define HID   128
#define NT    256
#define NROWS 3072
#define TPB   64
#define RPW   4                    // rows per warp
#define RPB   ((TPB/32)*RPW)       // 8 rows per block
#define NBLK  (NROWS/RPB)          // 384

typedef unsigned long long ull;

__device__ __forceinline__ ull fma2(ull a, ull b, ull c) {
    ull d;
    asm("fma.rn.f32x2 %0, %1, %2, %3;" : "=l"(d) : "l"(a), "l"(b), "l"(c));
    return d;
}
__device__ __forceinline__ ull add2(ull a, ull b) {
    ull d;
    asm("add.rn.f32x2 %0, %1, %2;" : "=l"(d) : "l"(a), "l"(b));
    return d;
}
__device__ __forceinline__ ull pack2(float lo, float hi) {
    ull d;
    asm("mov.b64 %0, {%1, %2};" : "=l"(d) : "f"(lo), "f"(hi));
    return d;
}
__device__ __forceinline__ void unpack2(ull v, float& lo, float& hi) {
    asm("mov.b64 {%0, %1}, %2;" : "=f"(lo), "=f"(hi) : "l"(v));
}

// accurate fast tanh: 1 - 2/(exp(2x)+1); ~1e-7 abs err, saturates at +/-inf.
__device__ __forceinline__ float tanh_fast(float x) {
    float e = __expf(2.0f * x);
    return 1.0f - __fdividef(2.0f, e + 1.0f);
}

// One f evaluation for the warp's 4 rows.
// in/kq: [row][quarter-f32x2]; weights via per-lane pointers (stride 32
// ulonglong2 = one [i] plane).
__device__ __forceinline__ void feval(
    const ull in[RPW][4], ull kq[RPW][4],
    const ulonglong2* __restrict__ w1aL, const ulonglong2* __restrict__ w1bL,
    const ulonglong2* __restrict__ w2aL, const ulonglong2* __restrict__ w2bL,
    const float* __restrict__ b1s, const ull b2q[4], int g)
{
#pragma unroll
    for (int r = 0; r < RPW; ++r)
#pragma unroll
        for (int d = 0; d < 4; ++d) kq[r][d] = 0ull;

#pragma unroll 4
    for (int i = 0; i < 16; ++i) {
        const ulonglong2 wa = w1aL[i * 32];   // W1[8s+0..3 , g+8i]
        const ulonglong2 wb = w1bL[i * 32];   // W1[8s+4..7 , g+8i]
        const float b1j = b1s[g + 8 * i];

        // per-quarter dots for the 4 rows
        float hs[RPW];
#pragma unroll
        for (int r = 0; r < RPW; ++r) {
            ull t0 = fma2(in[r][0], wa.x, 0ull);
            ull t1 = fma2(in[r][2], wb.x, 0ull);
            t0 = fma2(in[r][1], wa.y, t0);
            t1 = fma2(in[r][3], wb.y, t1);
            float lo, hi;
            unpack2(add2(t0, t1), lo, hi);
            hs[r] = lo + hi;
        }

        // butterfly over s (lanes ^8, ^16); 2 rows per packed value
        ull q01 = pack2(hs[0], hs[1]);
        ull q23 = pack2(hs[2], hs[3]);
        q01 = add2(q01, __shfl_xor_sync(0xffffffffu, q01, 8));
        q23 = add2(q23, __shfl_xor_sync(0xffffffffu, q23, 8));
        q01 = add2(q01, __shfl_xor_sync(0xffffffffu, q01, 16));
        q23 = add2(q23, __shfl_xor_sync(0xffffffffu, q23, 16));
        float f0, f1, f2, f3;
        unpack2(q01, f0, f1);
        unpack2(q23, f2, f3);

        const ulonglong2 va = w2aL[i * 32];   // W2[g+8i][8s+0..3]
        const ulonglong2 vb = w2bL[i * 32];   // W2[g+8i][8s+4..7]

        float hr[RPW];
        hr[0] = tanh_fast(f0 + b1j);
        hr[1] = tanh_fast(f1 + b1j);
        hr[2] = tanh_fast(f2 + b1j);
        hr[3] = tanh_fast(f3 + b1j);
#pragma unroll
        for (int r = 0; r < RPW; ++r) {
            const ull hh = pack2(hr[r], hr[r]);
            kq[r][0] = fma2(hh, va.x, kq[r][0]);
            kq[r][1] = fma2(hh, va.y, kq[r][1]);
            kq[r][2] = fma2(hh, vb.x, kq[r][2]);
            kq[r][3] = fma2(hh, vb.y, kq[r][3]);
        }
    }

    // reduce partial k over the 8 g-lanes (lanes ^1, ^2, ^4), then + b2
#pragma unroll
    for (int m = 1; m < 8; m <<= 1) {
#pragma unroll
        for (int r = 0; r < RPW; ++r)
#pragma unroll
            for (int d = 0; d < 4; ++d)
                kq[r][d] = add2(kq[r][d],
                                __shfl_xor_sync(0xffffffffu, kq[r][d], m));
    }
#pragma unroll
    for (int r = 0; r < RPW; ++r)
#pragma unroll
        for (int d = 0; d < 4; ++d) kq[r][d] = add2(kq[r][d], b2q[d]);
}

__global__ __launch_bounds__(TPB)
void rk4_mlp_kernel(
    const float* __restrict__ first_point,   // [3072, 32]
    const float* __restrict__ time_steps,    // [256]
    const float* __restrict__ W1,            // [32, 128]
    const float* __restrict__ b1,            // [128]
    const float* __restrict__ W2,            // [128, 32]
    const float* __restrict__ b2,            // [32]
    float* __restrict__ out)                 // [3072, 256, 32]
{
    // weight packs: [i][lane]; every warp LDS.128 is 512B all-unique
    __shared__ ulonglong2 w1qA[16][32];  // float4 = W1[8s+0..3 , g+8i]
    __shared__ ulonglong2 w1qB[16][32];  // float4 = W1[8s+4..7 , g+8i]
    __shared__ ulonglong2 w2qA[16][32];  // float4 = W2[g+8i][8s+0..3]
    __shared__ ulonglong2 w2qB[16][32];  // float4 = W2[g+8i][8s+4..7]
    __shared__ float b1s[HID];
    __shared__ float tss[NT];

    const int tid = threadIdx.x;

    // ---- stage weights (one-time; scalar writes) ----
    {
        float* a1 = (float*)w1qA; float* a2 = (float*)w1qB;
        float* a3 = (float*)w2qA; float* a4 = (float*)w2qB;
        for (int idx = tid; idx < 16 * 32 * 4; idx += TPB) {
            const int i  = idx >> 7;          // plane
            const int ln = (idx >> 2) & 31;   // lane
            const int f  = idx & 3;           // float within float4
            const int ss = ln >> 3, gg = ln & 7;
            const int j  = gg + 8 * i;
            a1[idx] = W1[(8 * ss + f)     * HID + j];
            a2[idx] = W1[(8 * ss + 4 + f) * HID + j];
            a3[idx] = W2[j * DIM + 8 * ss + f];
            a4[idx] = W2[j * DIM + 8 * ss + 4 + f];
        }
        for (int idx = tid; idx < HID; idx += TPB) b1s[idx] = b1[idx];
        for (int idx = tid; idx < NT;  idx += TPB) tss[idx] = time_steps[idx];
    }
    __syncthreads();

    const int lane = tid & 31;
    const int warp = tid >> 5;
    const int g = lane & 7;
    const int s = lane >> 3;
    const int rbase = blockIdx.x * RPB + warp * RPW;

    const ulonglong2* w1aL = &w1qA[0][lane];
    const ulonglong2* w1bL = &w1qB[0][lane];
    const ulonglong2* w2aL = &w2qA[0][lane];
    const ulonglong2* w2bL = &w2qB[0][lane];

    // b2 quarter, packed (registers)
    ull b2q[4];
#pragma unroll
    for (int d = 0; d < 4; ++d)
        b2q[d] = pack2(b2[8 * s + 2 * d], b2[8 * s + 2 * d + 1]);

    // ---- load initial state: lane's quarter for each of 4 rows ----
    ull y2[RPW][4], acc2[RPW][4], yin2[RPW][4], k2[RPW][4];
#pragma unroll
    for (int r = 0; r < RPW; ++r) {
        const ulonglong2* fp = reinterpret_cast<const ulonglong2*>(
            first_point + (size_t)(rbase + r) * DIM + 8 * s);
        ulonglong2 v0 = fp[0], v1 = fp[1];
        y2[r][0] = v0.x; y2[r][1] = v0.y;
        y2[r][2] = v1.x; y2[r][3] = v1.y;
    }

    // t = 0: lanes g<4 write row g's quarter (coalesced 128B per row)
    if (g < 4) {
        float* dst = out + (size_t)(rbase + g) * (NT * DIM) + 8 * s;
        ulonglong2 v0, v1;
        v0.x = y2[g][0]; v0.y = y2[g][1];
        v1.x = y2[g][2]; v1.y = y2[g][3];
        reinterpret_cast<ulonglong2*>(dst)[0] = v0;
        reinterpret_cast<ulonglong2*>(dst)[1] = v1;
    }

    // ---- RK4 time loop (sequential) ----
#pragma unroll 1
    for (int t = 0; t < NT - 1; ++t) {
        const float dt  = tss[t + 1] - tss[t];
        const ull dt6p = pack2(dt * (1.0f / 6.0f), dt * (1.0f / 6.0f));
        const ull dt3p = pack2(dt * (1.0f / 3.0f), dt * (1.0f / 3.0f));
        const ull dthp = pack2(0.5f * dt, 0.5f * dt);
        const ull dtfp = pack2(dt, dt);

        // k1
        feval(y2, k2, w1aL, w1bL, w2aL, w2bL, b1s, b2q, g);
#pragma unroll
        for (int r = 0; r < RPW; ++r)
#pragma unroll
            for (int d = 0; d < 4; ++d) {
                acc2[r][d] = fma2(dt6p, k2[r][d], y2[r][d]);
                yin2[r][d] = fma2(dthp, k2[r][d], y2[r][d]);
            }
        // k2
        feval(yin2, k2, w1aL, w1bL, w2aL, w2bL, b1s, b2q, g);
#pragma unroll
        for (int r = 0; r < RPW; ++r)
#pragma unroll
            for (int d = 0; d < 4; ++d) {
                acc2[r][d] = fma2(dt3p, k2[r][d], acc2[r][d]);
                yin2[r][d] = fma2(dthp, k2[r][d], y2[r][d]);
            }
        // k3
        feval(yin2, k2, w1aL, w1bL, w2aL, w2bL, b1s, b2q, g);
#pragma unroll
        for (int r = 0; r < RPW; ++r)
#pragma unroll
            for (int d = 0; d < 4; ++d) {
                acc2[r][d] = fma2(dt3p, k2[r][d], acc2[r][d]);
                yin2[r][d] = fma2(dtfp, k2[r][d], y2[r][d]);
            }
        // k4
        feval(yin2, k2, w1aL, w1bL, w2aL, w2bL, b1s, b2q, g);
#pragma unroll
        for (int r = 0; r < RPW; ++r)
#pragma unroll
            for (int d = 0; d < 4; ++d)
                y2[r][d] = fma2(dt6p, k2[r][d], acc2[r][d]);

        // store y_{t+1}
        if (g < 4) {
            float* dst = out + (size_t)(rbase + g) * (NT * DIM)
                       + (size_t)(t + 1) * DIM + 8 * s;
            ulonglong2 v0, v1;
            v0.x = y2[g][0]; v0.y = y2[g][1];
            v1.x = y2[g][2]; v1.y = y2[g][3];
            reinterpret_cast<ulonglong2*>(dst)[0] = v0;
            reinterpret_cast<ulonglong2*>(dst)[1] = v1;
        }
    }
}

extern "C" void kernel_launch(void* const* d_in, const int* in_sizes, int n_in,
                              void* d_out, int out_size) {
    const float* first_point = (const float*)d_in[0];  // [3,1024,32]
    const float* time_steps  = (const float*)d_in[1];  // [256]
    const float* W1          = (const float*)d_in[2];  // [32,128]
    const float* b1          = (const float*)d_in[3];  // [128]
    const float* W2          = (const float*)d_in[4];  // [128,32]
    const float* b2          = (const float*)d_in[5];  // [32]
    float* out = (float*)d_out;                        // [3,1024,256,32]

    rk4_mlp_kernel<<<NBLK, TPB>>>(first_point, time_steps, W1, b1, W2, b2, out);
}